// round 3
// baseline (speedup 1.0000x reference)
#include <cuda_runtime.h>
#include <math.h>

#define TT   500
#define BB   256
#define ENCN 700
#define HIDN 128
#define LCAP 128          // max firing enc per (b,t); density 5% of 700 -> mean 35, huge margin
#define NTHD 32768        // BB*HIDN

// ---------------- static device scratch (allocation-free rule) ----------------
__device__ float          g_w1t[ENCN * HIDN];                 // w1 transposed [enc][hid]
__device__ int            g_cnt [BB * TT];                    // firing count per (b,t)
__device__ unsigned short g_list[(size_t)BB * TT * LCAP];     // firing enc indices (ascending)
__device__ float          g_h   [(size_t)TT * BB * HIDN];     // layer-1 pre-filter activations
__device__ unsigned       g_s1  [(size_t)TT * BB * 4];        // layer-1 spike bitmasks (128 bits)
__device__ float          g_o   [TT * BB];                    // layer-2 pre-filter input

// Constants exactly as XLA-on-GPU computes them:
//   d  = __nv_expf(-0.05f)            (libdevice, matches jnp.exp on GPU bit-for-bit)
//   c1 = e/20 (RN div), cd1 = RN(c1*d)   [XLA constant-folds c*d]
//   cr = RN(-2*e)/20,   cdr = RN(cr*d)
__device__ __forceinline__ void snn_consts(float& d, float& cd1, float& cdr) {
    d        = expf(-0.05f);          // -> __nv_expf
    float e1 = expf(1.0f);            // -> __nv_expf
    float c1 = __fdiv_rn(e1, 20.0f);
    cd1      = __fmul_rn(c1, d);
    float cr = __fdiv_rn(__fmul_rn(-2.0f, e1), 20.0f);
    cdr      = __fmul_rn(cr, d);
}

// One scan step, replicating ptxas-contracted SASS of the XLA scan body:
//   q  = FFMA(d, q, FMUL(cd, p));  p = FFMA(d, p, in)
__device__ __forceinline__ void alpha_step(float d, float cd, float& p, float& q, float in) {
    q = fmaf(d, q, __fmul_rn(cd, p));
    p = fmaf(d, p, in);
}

// ---------------- K_t: transpose w1 [hid][enc] -> [enc][hid] ----------------
__global__ void k_transpose(const float* __restrict__ w1) {
    int i = blockIdx.x * blockDim.x + threadIdx.x;
    if (i < ENCN * HIDN) {
        int e = i >> 7;
        int h = i & (HIDN - 1);
        g_w1t[i] = w1[h * ENCN + e];
    }
}

// ---------------- K0: ballot-compact firing enc indices per (b,t) ----------------
__global__ __launch_bounds__(256) void k_compact(const float* __restrict__ x) {
    int b    = blockIdx.y;
    int t    = blockIdx.x * 8 + (threadIdx.x >> 5);
    int lane = threadIdx.x & 31;
    if (t >= TT) return;

    const float* xr = x + (size_t)b * (TT * ENCN) + (size_t)t * ENCN;
    size_t lbase = ((size_t)b * TT + t) * LCAP;
    int cnt = 0;
#pragma unroll
    for (int base = 0; base < ENCN; base += 32) {
        int e = base + lane;
        bool pred = (e < ENCN) && (__ldg(xr + e) > 0.5f);
        unsigned m = __ballot_sync(0xffffffffu, pred);
        if (pred) {
            int pos = cnt + __popc(m & ((1u << lane) - 1u));
            if (pos < LCAP) g_list[lbase + pos] = (unsigned short)e;
        }
        cnt += __popc(m);
    }
    if (lane == 0) g_cnt[b * TT + t] = cnt < LCAP ? cnt : LCAP;
}

// ---------------- K_A: sparse gather GEMM, w1t half cached in smem ----------------
// h[t,b,h] = serial ascending-enc sum of firing w1 columns
// (== cublas fp32 FFMA(x_k, w_k, acc) chain since x in {0,1}).
__global__ __launch_bounds__(256) void k_gather() {
    extern __shared__ float w1s[];   // [700][64] = 179200 B
    const int tc = blockIdx.x, b = blockIdx.y, hh = blockIdx.z;
    const int tid = threadIdx.x;

    for (int i = tid; i < ENCN * 64; i += 256) {
        int e = i >> 6, h = i & 63;
        w1s[i] = g_w1t[e * HIDN + hh * 64 + h];
    }
    __syncthreads();

    const int group = tid >> 6;      // 0..3, one t each
    const int hl    = tid & 63;

    for (int tt = group; tt < 125; tt += 4) {
        int t = tc * 125 + tt;
        int base = b * TT + t;
        int n = g_cnt[base];
        const unsigned short* lst = g_list + (size_t)base * LCAP;

        float acc = 0.0f;
        int i = 0;
        for (; i + 4 <= n; i += 4) {
            unsigned long long v = *(const unsigned long long*)(lst + i);
            int e0 = (int)(v & 0xffffu);
            int e1 = (int)((v >> 16) & 0xffffu);
            int e2 = (int)((v >> 32) & 0xffffu);
            int e3 = (int)(v >> 48);
            float a0 = w1s[e0 * 64 + hl];
            float a1 = w1s[e1 * 64 + hl];
            float a2 = w1s[e2 * 64 + hl];
            float a3 = w1s[e3 * 64 + hl];
            acc = __fadd_rn(acc, a0);
            acc = __fadd_rn(acc, a1);
            acc = __fadd_rn(acc, a2);
            acc = __fadd_rn(acc, a3);
        }
        for (; i < n; ++i)
            acc = __fadd_rn(acc, w1s[lst[i] * 64 + hl]);

        g_h[(size_t)t * (BB * HIDN) + b * HIDN + hh * 64 + hl] = acc;
    }
}

// ---------------- K_B: layer-1 alpha filter + spike scan, one thread per (b,h) ----------------
__global__ __launch_bounds__(256) void k_scan1() {
    int gid  = blockIdx.x * 256 + threadIdx.x;   // b*128 + h
    int b    = gid >> 7;
    int h    = gid & 127;
    int lane = threadIdx.x & 31;

    float d, cd1, cdr;
    snn_consts(d, cd1, cdr);

    float p1 = 0.f, q1 = 0.f, pr = 0.f, qr = 0.f;
    float hb[10];

    for (int t0 = 0; t0 < TT; t0 += 10) {
#pragma unroll
        for (int j = 0; j < 10; ++j)
            hb[j] = g_h[(size_t)(t0 + j) * NTHD + gid];
#pragma unroll
        for (int j = 0; j < 10; ++j) {
            // psp filter scan step (ptxas-contracted form)
            alpha_step(d, cd1, p1, q1, hb[j]);
            // refractory filter on past spikes
            qr = fmaf(d, qr, __fmul_rn(cdr, pr));
            float u = __fadd_rn(q1, qr);
            float s = (u >= 1.0f) ? 1.0f : 0.0f;
            pr = fmaf(d, pr, s);

            unsigned m = __ballot_sync(0xffffffffu, s != 0.0f);
            if (lane == 0)
                g_s1[((size_t)(t0 + j) * BB + b) * 4 + (h >> 5)] = m;
        }
    }
}

// ---------------- K_C: o[t,b] = serial ascending-h sum of s1*w2 ----------------
__global__ __launch_bounds__(256) void k_dot2(const float* __restrict__ w2) {
    __shared__ float w2s[HIDN];
    if (threadIdx.x < HIDN) w2s[threadIdx.x] = w2[threadIdx.x];
    __syncthreads();

    int idx = blockIdx.x * 256 + threadIdx.x;    // = t*256 + b
    uint4 m = *(const uint4*)(g_s1 + (size_t)idx * 4);

    float acc = 0.0f;
    unsigned w;
    w = m.x; while (w) { int i = __ffs(w) - 1; acc = __fadd_rn(acc, w2s[i]);       w &= w - 1; }
    w = m.y; while (w) { int i = __ffs(w) - 1; acc = __fadd_rn(acc, w2s[32 + i]);  w &= w - 1; }
    w = m.z; while (w) { int i = __ffs(w) - 1; acc = __fadd_rn(acc, w2s[64 + i]);  w &= w - 1; }
    w = m.w; while (w) { int i = __ffs(w) - 1; acc = __fadd_rn(acc, w2s[96 + i]);  w &= w - 1; }
    g_o[idx] = acc;
}

// ---------------- K_D: layer-2 filter + spike scan, one thread per b ----------------
__global__ __launch_bounds__(256) void k_scan2(float* __restrict__ out) {
    int b = threadIdx.x;

    float d, cd1, cdr;
    snn_consts(d, cd1, cdr);

    float p2 = 0.f, q2 = 0.f, pr2 = 0.f, qr2 = 0.f;
    float ob[10];

    for (int t0 = 0; t0 < TT; t0 += 10) {
#pragma unroll
        for (int j = 0; j < 10; ++j)
            ob[j] = g_o[(t0 + j) * BB + b];
#pragma unroll
        for (int j = 0; j < 10; ++j) {
            alpha_step(d, cd1, p2, q2, ob[j]);
            qr2 = fmaf(d, qr2, __fmul_rn(cdr, pr2));
            float u = __fadd_rn(q2, qr2);
            float s = (u >= 1.0f) ? 1.0f : 0.0f;
            pr2 = fmaf(d, pr2, s);
            out[b * TT + (t0 + j)] = s;
        }
    }
}

// ---------------- launch ----------------
extern "C" void kernel_launch(void* const* d_in, const int* in_sizes, int n_in,
                              void* d_out, int out_size) {
    const float* x = nullptr, *w1 = nullptr, *w2 = nullptr;
    for (int i = 0; i < n_in; ++i) {
        if      (in_sizes[i] == BB * TT * ENCN) x  = (const float*)d_in[i];
        else if (in_sizes[i] == HIDN * ENCN)    w1 = (const float*)d_in[i];
        else if (in_sizes[i] == HIDN)           w2 = (const float*)d_in[i];
    }

    static int smem_set = 0;
    if (!smem_set) {
        cudaFuncSetAttribute(k_gather, cudaFuncAttributeMaxDynamicSharedMemorySize,
                             ENCN * 64 * (int)sizeof(float));
        smem_set = 1;
    }

    k_transpose<<<(ENCN * HIDN + 255) / 256, 256>>>(w1);
    k_compact<<<dim3((TT + 7) / 8, BB), 256>>>(x);
    k_gather<<<dim3(4, BB, 2), 256, ENCN * 64 * sizeof(float)>>>();
    k_scan1<<<NTHD / 256, 256>>>();
    k_dot2<<<TT, 256>>>(w2);
    k_scan2<<<1, BB>>>((float*)d_out);
}

// round 4
// speedup vs baseline: 1.5537x; 1.5537x over previous
#include <cuda_runtime.h>
#include <math.h>

#define TT   500
#define BB   256
#define ENCN 700
#define HIDN 128
#define LCAP 128          // max firing enc per (b,t); density 5% of 700 -> mean 35, huge margin
#define NTHD 32768        // BB*HIDN

// ---------------- static device scratch (allocation-free rule) ----------------
__device__ float          g_w1t[ENCN * HIDN];                 // w1 transposed [enc][hid]
__device__ int            g_cnt [BB * TT];                    // firing count per (b,t)
__device__ unsigned short g_list[(size_t)BB * TT * LCAP];     // firing enc indices (ascending)
__device__ float          g_h   [(size_t)TT * BB * HIDN];     // layer-1 pre-filter activations
__device__ unsigned       g_s1  [(size_t)TT * BB * 4];        // layer-1 spike bitmasks (128 bits)
__device__ float          g_o   [TT * BB];                    // layer-2 pre-filter input

// Constants exactly as XLA-on-GPU computes them (DO NOT TOUCH — bit-exact vs reference):
__device__ __forceinline__ void snn_consts(float& d, float& cd1, float& cdr) {
    d        = expf(-0.05f);          // libdevice __nv_expf
    float e1 = expf(1.0f);
    float c1 = __fdiv_rn(e1, 20.0f);
    cd1      = __fmul_rn(c1, d);
    float cr = __fdiv_rn(__fmul_rn(-2.0f, e1), 20.0f);
    cdr      = __fmul_rn(cr, d);
}

// ptxas-contracted scan step (bit-exact vs reference — DO NOT TOUCH):
__device__ __forceinline__ void alpha_step(float d, float cd, float& p, float& q, float in) {
    q = fmaf(d, q, __fmul_rn(cd, p));
    p = fmaf(d, p, in);
}

// ---------------- K_t: transpose w1 [hid][enc] -> [enc][hid] ----------------
__global__ void k_transpose(const float* __restrict__ w1) {
    int i = blockIdx.x * blockDim.x + threadIdx.x;
    if (i < ENCN * HIDN) {
        int e = i >> 7;
        int h = i & (HIDN - 1);
        g_w1t[i] = w1[h * ENCN + e];
    }
}

// ---------------- K0: ballot-compact firing enc indices per (b,t) ----------------
__global__ __launch_bounds__(256) void k_compact(const float* __restrict__ x) {
    int b    = blockIdx.y;
    int t    = blockIdx.x * 8 + (threadIdx.x >> 5);
    int lane = threadIdx.x & 31;
    if (t >= TT) return;

    const float* xr = x + (size_t)b * (TT * ENCN) + (size_t)t * ENCN;

    // issue all 22 loads up front (MLP=22), then serial ballots
    float v[22];
#pragma unroll
    for (int r = 0; r < 22; ++r) {
        int e = r * 32 + lane;
        v[r] = (e < ENCN) ? __ldg(xr + e) : 0.0f;
    }

    size_t lbase = ((size_t)b * TT + t) * LCAP;
    int cnt = 0;
#pragma unroll
    for (int r = 0; r < 22; ++r) {
        bool pred = v[r] > 0.5f;
        unsigned m = __ballot_sync(0xffffffffu, pred);
        if (pred) {
            int pos = cnt + __popc(m & ((1u << lane) - 1u));
            if (pos < LCAP) g_list[lbase + pos] = (unsigned short)(r * 32 + lane);
        }
        cnt += __popc(m);
    }
    if (lane == 0) g_cnt[b * TT + t] = cnt < LCAP ? cnt : LCAP;
}

// ---------------- K_A: sparse gather GEMM ----------------
// smem tile = 32 hid cols (89.6KB) -> 2 blocks/SM; warp-per-t -> 8 independent
// serial chains per block (16/SM). grid (2 t-chunks, B, 4 hid-quarters).
// h[t,b,h] = serial ascending-enc sum of firing w1 columns (bit-exact vs SGEMM).
__global__ __launch_bounds__(256) void k_gather() {
    extern __shared__ float w1s[];   // [700][32] = 89600 B
    const int tc = blockIdx.x, b = blockIdx.y, hq = blockIdx.z;
    const int tid  = threadIdx.x;
    const int wid  = tid >> 5;
    const int lane = tid & 31;

    // fill smem with this hid-quarter of w1t (coalesced 128B per warp-load)
    for (int i = tid; i < ENCN * 32; i += 256) {
        int e = i >> 5, h = i & 31;
        w1s[i] = g_w1t[e * HIDN + hq * 32 + h];
    }
    __syncthreads();

    const int tend = tc * 250 + 250;
    for (int t = tc * 250 + wid; t < tend; t += 8) {
        int base = b * TT + t;
        int n = __ldg(g_cnt + base);
        const unsigned short* lst = g_list + (size_t)base * LCAP;

        float acc = 0.0f;
        int i = 0;
        for (; i + 4 <= n; i += 4) {
            unsigned long long v = *(const unsigned long long*)(lst + i);
            int e0 = (int)(v & 0xffffu);
            int e1 = (int)((v >> 16) & 0xffffu);
            int e2 = (int)((v >> 32) & 0xffffu);
            int e3 = (int)(v >> 48);
            float a0 = w1s[e0 * 32 + lane];
            float a1 = w1s[e1 * 32 + lane];
            float a2 = w1s[e2 * 32 + lane];
            float a3 = w1s[e3 * 32 + lane];
            acc = __fadd_rn(acc, a0);
            acc = __fadd_rn(acc, a1);
            acc = __fadd_rn(acc, a2);
            acc = __fadd_rn(acc, a3);
        }
        for (; i < n; ++i)
            acc = __fadd_rn(acc, w1s[lst[i] * 32 + lane]);

        g_h[(size_t)t * NTHD + b * HIDN + hq * 32 + lane] = acc;
    }
}

// ---------------- K_B: layer-1 filter + spike scan, one thread per (b,h) ----------------
// Register double-buffering: next batch's loads issue before current batch's compute.
__global__ __launch_bounds__(256) void k_scan1() {
    int gid  = blockIdx.x * 256 + threadIdx.x;   // b*128 + h
    int b    = gid >> 7;
    int h    = gid & 127;
    int lane = threadIdx.x & 31;

    float d, cd1, cdr;
    snn_consts(d, cd1, cdr);

    float p1 = 0.f, q1 = 0.f, pr = 0.f, qr = 0.f;
    float bufA[10], bufB[10];

#pragma unroll
    for (int j = 0; j < 10; ++j)
        bufA[j] = __ldg(&g_h[(size_t)j * NTHD + gid]);

    for (int t0 = 0; t0 < TT; t0 += 20) {
        // prefetch batch B (t0+10..t0+19) while computing batch A
#pragma unroll
        for (int j = 0; j < 10; ++j)
            bufB[j] = (t0 + 10 + j < TT) ? __ldg(&g_h[(size_t)(t0 + 10 + j) * NTHD + gid]) : 0.0f;
#pragma unroll
        for (int j = 0; j < 10; ++j) {
            alpha_step(d, cd1, p1, q1, bufA[j]);
            qr = fmaf(d, qr, __fmul_rn(cdr, pr));
            float u = __fadd_rn(q1, qr);
            float s = (u >= 1.0f) ? 1.0f : 0.0f;
            pr = fmaf(d, pr, s);
            unsigned m = __ballot_sync(0xffffffffu, s != 0.0f);
            if (lane == 0)
                g_s1[((size_t)(t0 + j) * BB + b) * 4 + (h >> 5)] = m;
        }
        // prefetch batch A (t0+20..t0+29) while computing batch B
#pragma unroll
        for (int j = 0; j < 10; ++j)
            bufA[j] = (t0 + 20 + j < TT) ? __ldg(&g_h[(size_t)(t0 + 20 + j) * NTHD + gid]) : 0.0f;
#pragma unroll
        for (int j = 0; j < 10; ++j) {
            alpha_step(d, cd1, p1, q1, bufB[j]);
            qr = fmaf(d, qr, __fmul_rn(cdr, pr));
            float u = __fadd_rn(q1, qr);
            float s = (u >= 1.0f) ? 1.0f : 0.0f;
            pr = fmaf(d, pr, s);
            unsigned m = __ballot_sync(0xffffffffu, s != 0.0f);
            if (lane == 0)
                g_s1[((size_t)(t0 + 10 + j) * BB + b) * 4 + (h >> 5)] = m;
        }
    }
}

// ---------------- K_C: o[t,b] = serial ascending-h sum of s1*w2 ----------------
__global__ __launch_bounds__(256) void k_dot2(const float* __restrict__ w2) {
    __shared__ float w2s[HIDN];
    if (threadIdx.x < HIDN) w2s[threadIdx.x] = w2[threadIdx.x];
    __syncthreads();

    int idx = blockIdx.x * 256 + threadIdx.x;    // = t*256 + b
    uint4 m = *(const uint4*)(g_s1 + (size_t)idx * 4);

    float acc = 0.0f;
    unsigned w;
    w = m.x; while (w) { int i = __ffs(w) - 1; acc = __fadd_rn(acc, w2s[i]);       w &= w - 1; }
    w = m.y; while (w) { int i = __ffs(w) - 1; acc = __fadd_rn(acc, w2s[32 + i]);  w &= w - 1; }
    w = m.z; while (w) { int i = __ffs(w) - 1; acc = __fadd_rn(acc, w2s[64 + i]);  w &= w - 1; }
    w = m.w; while (w) { int i = __ffs(w) - 1; acc = __fadd_rn(acc, w2s[96 + i]);  w &= w - 1; }
    g_o[idx] = acc;
}

// ---------------- K_D: layer-2 filter + spike scan, one thread per b ----------------
__global__ __launch_bounds__(BB) void k_scan2(float* __restrict__ out) {
    int b = threadIdx.x;

    float d, cd1, cdr;
    snn_consts(d, cd1, cdr);

    float p2 = 0.f, q2 = 0.f, pr2 = 0.f, qr2 = 0.f;
    float bufA[10], bufB[10];

#pragma unroll
    for (int j = 0; j < 10; ++j) bufA[j] = g_o[j * BB + b];

    for (int t0 = 0; t0 < TT; t0 += 20) {
#pragma unroll
        for (int j = 0; j < 10; ++j)
            bufB[j] = (t0 + 10 + j < TT) ? g_o[(t0 + 10 + j) * BB + b] : 0.0f;
#pragma unroll
        for (int j = 0; j < 10; ++j) {
            alpha_step(d, cd1, p2, q2, bufA[j]);
            qr2 = fmaf(d, qr2, __fmul_rn(cdr, pr2));
            float u = __fadd_rn(q2, qr2);
            float s = (u >= 1.0f) ? 1.0f : 0.0f;
            pr2 = fmaf(d, pr2, s);
            out[b * TT + (t0 + j)] = s;
        }
#pragma unroll
        for (int j = 0; j < 10; ++j)
            bufA[j] = (t0 + 20 + j < TT) ? g_o[(t0 + 20 + j) * BB + b] : 0.0f;
#pragma unroll
        for (int j = 0; j < 10; ++j) {
            alpha_step(d, cd1, p2, q2, bufB[j]);
            qr2 = fmaf(d, qr2, __fmul_rn(cdr, pr2));
            float u = __fadd_rn(q2, qr2);
            float s = (u >= 1.0f) ? 1.0f : 0.0f;
            pr2 = fmaf(d, pr2, s);
            out[b * TT + (t0 + 10 + j)] = s;
        }
    }
}

// ---------------- launch ----------------
extern "C" void kernel_launch(void* const* d_in, const int* in_sizes, int n_in,
                              void* d_out, int out_size) {
    const float* x = nullptr, *w1 = nullptr, *w2 = nullptr;
    for (int i = 0; i < n_in; ++i) {
        if      (in_sizes[i] == BB * TT * ENCN) x  = (const float*)d_in[i];
        else if (in_sizes[i] == HIDN * ENCN)    w1 = (const float*)d_in[i];
        else if (in_sizes[i] == HIDN)           w2 = (const float*)d_in[i];
    }

    static int smem_set = 0;
    if (!smem_set) {
        cudaFuncSetAttribute(k_gather, cudaFuncAttributeMaxDynamicSharedMemorySize,
                             ENCN * 32 * (int)sizeof(float));
        smem_set = 1;
    }

    k_transpose<<<(ENCN * HIDN + 255) / 256, 256>>>(w1);
    k_compact<<<dim3((TT + 7) / 8, BB), 256>>>(x);
    k_gather<<<dim3(2, BB, 4), 256, ENCN * 32 * sizeof(float)>>>();
    k_scan1<<<NTHD / 256, 256>>>();
    k_dot2<<<TT, 256>>>(w2);
    k_scan2<<<1, BB>>>((float*)d_out);
}

// round 5
// speedup vs baseline: 2.1536x; 1.3862x over previous
#include <cuda_runtime.h>
#include <math.h>

#define TT   500
#define BB   256
#define ENCN 700
#define HIDN 128
#define LCAP 128          // max firing enc per (b,t); density 5% of 700 -> mean 35, huge margin
#define NTHD 32768        // BB*HIDN

// ---------------- static device scratch (allocation-free rule) ----------------
__device__ float          g_w1t[ENCN * HIDN];                 // w1 transposed [enc][hid]
__device__ int            g_cnt [BB * TT];                    // firing count per (b,t)
__device__ unsigned short g_list[(size_t)BB * TT * LCAP];     // firing enc indices (ascending)
__device__ float          g_h   [(size_t)TT * BB * HIDN];     // layer-1 pre-filter activations
__device__ float          g_s1f [(size_t)TT * BB * HIDN];     // layer-1 spikes as floats
__device__ float          g_o   [TT * BB];                    // layer-2 pre-filter input

// Constants exactly as XLA-on-GPU computes them (bit-exact vs reference — DO NOT TOUCH):
__device__ __forceinline__ void snn_consts(float& d, float& cd1, float& cdr) {
    d        = expf(-0.05f);          // libdevice __nv_expf
    float e1 = expf(1.0f);
    float c1 = __fdiv_rn(e1, 20.0f);
    cd1      = __fmul_rn(c1, d);
    float cr = __fdiv_rn(__fmul_rn(-2.0f, e1), 20.0f);
    cdr      = __fmul_rn(cr, d);
}

// ptxas-contracted scan step (bit-exact vs reference — DO NOT TOUCH):
__device__ __forceinline__ void alpha_step(float d, float cd, float& p, float& q, float in) {
    q = fmaf(d, q, __fmul_rn(cd, p));
    p = fmaf(d, p, in);
}

// ---------------- K_t: transpose w1 [hid][enc] -> [enc][hid] ----------------
__global__ void k_transpose(const float* __restrict__ w1) {
    int i = blockIdx.x * blockDim.x + threadIdx.x;
    if (i < ENCN * HIDN) {
        int e = i >> 7;
        int h = i & (HIDN - 1);
        g_w1t[i] = w1[h * ENCN + e];
    }
}

// ---------------- K0: ballot-compact firing enc indices per (b,t) ----------------
__global__ __launch_bounds__(256) void k_compact(const float* __restrict__ x) {
    int b    = blockIdx.y;
    int t    = blockIdx.x * 8 + (threadIdx.x >> 5);
    int lane = threadIdx.x & 31;
    if (t >= TT) return;

    const float* xr = x + (size_t)b * (TT * ENCN) + (size_t)t * ENCN;

    // issue all 22 loads up front (MLP=22), then serial ballots
    float v[22];
#pragma unroll
    for (int r = 0; r < 22; ++r) {
        int e = r * 32 + lane;
        v[r] = (e < ENCN) ? __ldg(xr + e) : 0.0f;
    }

    size_t lbase = ((size_t)b * TT + t) * LCAP;
    int cnt = 0;
#pragma unroll
    for (int r = 0; r < 22; ++r) {
        bool pred = v[r] > 0.5f;
        unsigned m = __ballot_sync(0xffffffffu, pred);
        if (pred) {
            int pos = cnt + __popc(m & ((1u << lane) - 1u));
            if (pos < LCAP) g_list[lbase + pos] = (unsigned short)(r * 32 + lane);
        }
        cnt += __popc(m);
    }
    if (lane == 0) g_cnt[b * TT + t] = cnt < LCAP ? cnt : LCAP;
}

// ---------------- K_A: sparse gather GEMM ----------------
// smem tile = 32 hid cols (89.6KB) -> 2 blocks/SM; 512 thr = 16 warps, warp-per-t
// -> 32 independent serial chains per SM. grid (2 t-chunks, B, 4 hid-quarters).
// h[t,b,h] = serial ascending-enc sum of firing w1 columns (bit-exact vs SGEMM).
__global__ __launch_bounds__(512) void k_gather() {
    extern __shared__ float w1s[];   // [700][32] = 89600 B
    const int tc = blockIdx.x, b = blockIdx.y, hq = blockIdx.z;
    const int tid  = threadIdx.x;
    const int wid  = tid >> 5;
    const int lane = tid & 31;

    // fill smem with this hid-quarter of w1t (coalesced 128B per warp-load)
    for (int i = tid; i < ENCN * 32; i += 512) {
        int e = i >> 5, h = i & 31;
        w1s[i] = g_w1t[e * HIDN + hq * 32 + h];
    }
    __syncthreads();

    const int tend = tc * 250 + 250;
    for (int t = tc * 250 + wid; t < tend; t += 16) {
        int base = b * TT + t;
        int n = __ldg(g_cnt + base);
        const unsigned short* lst = g_list + (size_t)base * LCAP;

        float acc = 0.0f;
        int i = 0;
        for (; i + 4 <= n; i += 4) {
            unsigned long long v = *(const unsigned long long*)(lst + i);
            int e0 = (int)(v & 0xffffu);
            int e1 = (int)((v >> 16) & 0xffffu);
            int e2 = (int)((v >> 32) & 0xffffu);
            int e3 = (int)(v >> 48);
            float a0 = w1s[e0 * 32 + lane];
            float a1 = w1s[e1 * 32 + lane];
            float a2 = w1s[e2 * 32 + lane];
            float a3 = w1s[e3 * 32 + lane];
            acc = __fadd_rn(acc, a0);
            acc = __fadd_rn(acc, a1);
            acc = __fadd_rn(acc, a2);
            acc = __fadd_rn(acc, a3);
        }
        for (; i < n; ++i)
            acc = __fadd_rn(acc, w1s[lst[i] * 32 + lane]);

        g_h[(size_t)t * NTHD + b * HIDN + hq * 32 + lane] = acc;
    }
}

// ---------------- K_B: layer-1 filter + spike scan, one thread per (b,h) ----------------
// No ballot in the recurrence; spikes stored as floats. (256,1) keeps buffers in regs.
__global__ __launch_bounds__(256, 1) void k_scan1() {
    int gid = blockIdx.x * 256 + threadIdx.x;   // b*128 + h

    float d, cd1, cdr;
    snn_consts(d, cd1, cdr);

    float p1 = 0.f, q1 = 0.f, pr = 0.f, qr = 0.f;
    float bufA[10], bufB[10];

#pragma unroll
    for (int j = 0; j < 10; ++j)
        bufA[j] = __ldg(&g_h[(size_t)j * NTHD + gid]);

    for (int t0 = 0; t0 < TT; t0 += 20) {
        // prefetch batch B (t0+10..t0+19) while computing batch A
#pragma unroll
        for (int j = 0; j < 10; ++j)
            bufB[j] = (t0 + 10 + j < TT) ? __ldg(&g_h[(size_t)(t0 + 10 + j) * NTHD + gid]) : 0.0f;
#pragma unroll
        for (int j = 0; j < 10; ++j) {
            alpha_step(d, cd1, p1, q1, bufA[j]);
            qr = fmaf(d, qr, __fmul_rn(cdr, pr));
            float u = __fadd_rn(q1, qr);
            float s = (u >= 1.0f) ? 1.0f : 0.0f;
            pr = fmaf(d, pr, s);
            g_s1f[(size_t)(t0 + j) * NTHD + gid] = s;
        }
        // prefetch batch A (t0+20..t0+29) while computing batch B
#pragma unroll
        for (int j = 0; j < 10; ++j)
            bufA[j] = (t0 + 20 + j < TT) ? __ldg(&g_h[(size_t)(t0 + 20 + j) * NTHD + gid]) : 0.0f;
#pragma unroll
        for (int j = 0; j < 10; ++j) {
            alpha_step(d, cd1, p1, q1, bufB[j]);
            qr = fmaf(d, qr, __fmul_rn(cdr, pr));
            float u = __fadd_rn(q1, qr);
            float s = (u >= 1.0f) ? 1.0f : 0.0f;
            pr = fmaf(d, pr, s);
            g_s1f[(size_t)(t0 + 10 + j) * NTHD + gid] = s;
        }
    }
}

// ---------------- K_C: o[t,b] = serial ascending-h FFMA over float spikes ----------------
// fmaf(s,w,acc) with s in {0,1} is bit-identical to the reference serial-k GEMV.
__global__ __launch_bounds__(256) void k_dot2(const float* __restrict__ w2) {
    __shared__ float w2s[HIDN];
    if (threadIdx.x < HIDN) w2s[threadIdx.x] = w2[threadIdx.x];
    __syncthreads();

    int t = blockIdx.x;
    int b = threadIdx.x;
    const float4* sp = (const float4*)(g_s1f + (size_t)t * NTHD + b * HIDN);

    float acc = 0.0f;
#pragma unroll
    for (int j = 0; j < 32; ++j) {
        float4 v = __ldg(sp + j);
        acc = fmaf(v.x, w2s[4 * j + 0], acc);
        acc = fmaf(v.y, w2s[4 * j + 1], acc);
        acc = fmaf(v.z, w2s[4 * j + 2], acc);
        acc = fmaf(v.w, w2s[4 * j + 3], acc);
    }
    g_o[t * BB + b] = acc;
}

// ---------------- K_D: layer-2 filter + spike scan, one thread per b ----------------
__global__ __launch_bounds__(BB, 1) void k_scan2(float* __restrict__ out) {
    int b = threadIdx.x;

    float d, cd1, cdr;
    snn_consts(d, cd1, cdr);

    float p2 = 0.f, q2 = 0.f, pr2 = 0.f, qr2 = 0.f;
    float bufA[10], bufB[10];

#pragma unroll
    for (int j = 0; j < 10; ++j) bufA[j] = g_o[j * BB + b];

    for (int t0 = 0; t0 < TT; t0 += 20) {
#pragma unroll
        for (int j = 0; j < 10; ++j)
            bufB[j] = (t0 + 10 + j < TT) ? g_o[(t0 + 10 + j) * BB + b] : 0.0f;
#pragma unroll
        for (int j = 0; j < 10; ++j) {
            alpha_step(d, cd1, p2, q2, bufA[j]);
            qr2 = fmaf(d, qr2, __fmul_rn(cdr, pr2));
            float u = __fadd_rn(q2, qr2);
            float s = (u >= 1.0f) ? 1.0f : 0.0f;
            pr2 = fmaf(d, pr2, s);
            out[b * TT + (t0 + j)] = s;
        }
#pragma unroll
        for (int j = 0; j < 10; ++j)
            bufA[j] = (t0 + 20 + j < TT) ? g_o[(t0 + 20 + j) * BB + b] : 0.0f;
#pragma unroll
        for (int j = 0; j < 10; ++j) {
            alpha_step(d, cd1, p2, q2, bufB[j]);
            qr2 = fmaf(d, qr2, __fmul_rn(cdr, pr2));
            float u = __fadd_rn(q2, qr2);
            float s = (u >= 1.0f) ? 1.0f : 0.0f;
            pr2 = fmaf(d, pr2, s);
            out[b * TT + (t0 + 10 + j)] = s;
        }
    }
}

// ---------------- launch ----------------
extern "C" void kernel_launch(void* const* d_in, const int* in_sizes, int n_in,
                              void* d_out, int out_size) {
    const float* x = nullptr, *w1 = nullptr, *w2 = nullptr;
    for (int i = 0; i < n_in; ++i) {
        if      (in_sizes[i] == BB * TT * ENCN) x  = (const float*)d_in[i];
        else if (in_sizes[i] == HIDN * ENCN)    w1 = (const float*)d_in[i];
        else if (in_sizes[i] == HIDN)           w2 = (const float*)d_in[i];
    }

    static int smem_set = 0;
    if (!smem_set) {
        cudaFuncSetAttribute(k_gather, cudaFuncAttributeMaxDynamicSharedMemorySize,
                             ENCN * 32 * (int)sizeof(float));
        smem_set = 1;
    }

    k_transpose<<<(ENCN * HIDN + 255) / 256, 256>>>(w1);
    k_compact<<<dim3((TT + 7) / 8, BB), 256>>>(x);
    k_gather<<<dim3(2, BB, 4), 512, ENCN * 32 * sizeof(float)>>>();
    k_scan1<<<NTHD / 256, 256>>>();
    k_dot2<<<TT, BB>>>(w2);
    k_scan2<<<1, BB>>>((float*)d_out);
}